// round 12
// baseline (speedup 1.0000x reference)
#include <cuda_runtime.h>
#include <cuda_bf16.h>
#include <math_constants.h>

// Problem constants
#define NPTS    8192
#define KCOMP   64
#define NBINS   256
#define WPB     8                 // warps (j's) per main block
#define NMAIN   1024              // main blocks; block 0 is the prep block
#define GRID    (NMAIN + 1)
#define HSTR    257               // padded stride, 8 warp-private hists (bank-safe)

// KDE: bw = 0.5*128/8192 = 2^-7 exactly  ->  exp(-8192*d^2) = exp2(CKDE*d^2)
#define LOG2E 1.4426950408889634
__device__ __constant__ float CKDE = (float)(-8192.0 * LOG2E);
__device__ __constant__ float NORM = (float)(1.0 / (2.5066282746310002 * 0.0078125 * 8192.0));
// ex2.ftz -> exact 0 for |d| > 0.10327. Fixed bins: width 0.052, +/-2-bin window
// covers +/-0.104 > R. Edge clamping only EXTENDS windows -> correct for any input.
#define BIN_LO  (-6.656f)
#define BIN_IW  (19.230769230769230769f)   // 1/0.052

// Scratch (device globals — no allocation allowed)
__device__ __align__(16) float g_xs[NPTS];   // x counting-sorted by bin
__device__ int            g_binstart[NBINS + 1];
__device__ float          g_bsum[GRID];
__device__ volatile int   g_flag   = 0;      // prep-done flag; reset each call
__device__ int            g_ticket = 0;      // last-block ticket; reset each call

__device__ __forceinline__ float ex2(float x) {
    float r;
    asm("ex2.approx.ftz.f32 %0, %1;" : "=f"(r) : "f"(x));
    return r;
}

__device__ __forceinline__ int bin_of(float v) {
    int b = (int)floorf((v - BIN_LO) * BIN_IW);
    return max(min(b, NBINS - 1), 0);
}

__global__ __launch_bounds__(256)
void gmm_fused(const float* __restrict__ x,  const float* __restrict__ wl,
               const float* __restrict__ mu, const float* __restrict__ lv,
               float* __restrict__ out) {
    __shared__ int   h[HSTR * 8];        // prep: warp-private hists -> cursors
    __shared__ int   tot[NBINS];
    __shared__ int   bs[NBINS + 1];
    __shared__ float smn[KCOMP], scf[KCOMP], sa[KCOMP];
    __shared__ float wsum[WPB];
    __shared__ float rs[256];
    __shared__ int   s_last;

    const int tid  = threadIdx.x;
    const int lane = tid & 31;
    const int w    = tid >> 5;
    const int blk  = blockIdx.x;

    if (blk == 0) {
        // ================= PREP (sole producer) =================
        for (int i = tid; i < HSTR * 8; i += 256) h[i] = 0;
        __syncthreads();

        // pass 1: warp-private histograms (spread across 8 hists)
        #pragma unroll 4
        for (int e = 0; e < 32; e++) {
            float v = x[tid + e * 256];
            atomicAdd(&h[bin_of(v) + HSTR * w], 1);
        }
        __syncthreads();

        // cross-warp exclusive prefix per bin (thread-per-bin, in place)
        {
            int run = 0;
            #pragma unroll
            for (int k = 0; k < 8; k++) {
                int idx = tid + HSTR * k;
                int v = h[idx];
                h[idx] = run;
                run += v;
            }
            tot[tid] = run;
        }
        __syncthreads();

        // warp 0: exclusive scan of 256 bin totals
        if (w == 0) {
            int v[8], p[8], run = 0;
            #pragma unroll
            for (int k = 0; k < 8; k++) {
                v[k] = tot[lane * 8 + k];
                p[k] = run;
                run += v[k];
            }
            int incl = run;
            #pragma unroll
            for (int o = 1; o < 32; o <<= 1) {
                int u = __shfl_up_sync(0xffffffffu, incl, o);
                if (lane >= o) incl += u;
            }
            int excl = incl - run;
            #pragma unroll
            for (int k = 0; k < 8; k++) bs[lane * 8 + k] = excl + p[k];
            if (lane == 31) bs[NBINS] = incl;      // == NPTS
        }
        __syncthreads();

        // convert warp prefixes to absolute scatter cursors
        {
            int base = bs[tid];
            #pragma unroll
            for (int k = 0; k < 8; k++) h[tid + HSTR * k] += base;
        }
        g_binstart[tid] = bs[tid];
        if (tid == 0) g_binstart[NBINS] = bs[NBINS];
        __syncthreads();

        // pass 2: scatter via cursor atomics (same elements -> unique positions)
        #pragma unroll 4
        for (int e = 0; e < 32; e++) {
            float v = x[tid + e * 256];
            int pos = atomicAdd(&h[bin_of(v) + HSTR * w], 1);
            g_xs[pos] = v;
        }
        __syncthreads();

        if (tid == 0) {
            g_bsum[0] = 0.0f;
            __threadfence();                        // release all prep writes
            atomicExch((int*)&g_flag, 1);
        }
    } else {
        // ================= MAIN (overlaps with prep) =================
        // redundant softmax constants (race-free: direct global reads of const inputs)
        if (tid < KCOMP) {
            float m = -CUDART_INF_F;
            #pragma unroll
            for (int i = 0; i < KCOMP; i++) m = fmaxf(m, __ldg(&wl[i]));
            float ss = 0.0f;
            #pragma unroll
            for (int i = 0; i < KCOMP; i++) ss += __expf(__ldg(&wl[i]) - m);
            float wgt = __expf(__ldg(&wl[tid]) - m) / ss;
            float var = __expf(lv[tid]);
            smn[tid] = mu[tid];
            scf[tid] = wgt * rsqrtf(6.283185307179586f * var);
            sa[tid]  = (float)(-0.5 * LOG2E) / var;
        }
        __syncthreads();

        // j from ORIGINAL x (no prep dependency): sum over j is permutation-invariant
        const int j = (blk - 1) * WPB + w;
        const float xj = __ldg(&x[j]);

        // mixture pdf partial (2 comps/lane) — computed BEFORE waiting on prep
        float d1 = xj - smn[lane];
        float mixp = scf[lane] * ex2(sa[lane] * d1 * d1);
        float d2 = xj - smn[lane + 32];
        mixp += scf[lane + 32] * ex2(sa[lane + 32] * d2 * d2);

        // wait for prep (volatile poll by one thread, acquire fence, release block)
        if (tid == 0) {
            while (g_flag == 0) { }
            __threadfence();
        }
        __syncthreads();

        // KDE window loop. NOTE: plain coherent loads of g_binstart/g_xs —
        // they are written THIS launch; __ldg here is UB (the R11 bug).
        int b  = bin_of(xj);
        int c0 = g_binstart[max(b - 2, 0)];
        int c1 = g_binstart[min(b + 3, NBINS)];

        const float ck = CKDE;
        float acc = 0.0f;
        #pragma unroll 4
        for (int i = c0 + lane; i < c1; i += 32) {
            float d = xj - g_xs[i];          // Sterbenz-exact for close pairs
            acc += ex2(ck * d * d);
        }

        // fold before reducing: sum_lanes(mixp - NORM*acc) = mixture_j - data_j
        float t = mixp - NORM * acc;
        #pragma unroll
        for (int o = 16; o > 0; o >>= 1) t += __shfl_xor_sync(0xffffffffu, t, o);
        if (lane == 0) wsum[w] = t * t;
        __syncthreads();

        if (tid == 0) {
            float v = 0.0f;
            #pragma unroll
            for (int p = 0; p < WPB; p++) v += wsum[p];
            g_bsum[blk] = v;
        }
    }

    // ================= ticket + deterministic final reduction =================
    if (tid == 0) {
        __threadfence();
        int tk = atomicAdd(&g_ticket, 1);
        s_last = (tk == GRID - 1);
    }
    __syncthreads();

    if (s_last) {
        __threadfence();                     // acquire: order reads after ticket
        float v = 0.0f;
        for (int i = tid; i < GRID; i += 256) v += g_bsum[i];
        rs[tid] = v;
        __syncthreads();
        #pragma unroll
        for (int off = 128; off > 0; off >>= 1) {
            if (tid < off) rs[tid] += rs[tid + off];
            __syncthreads();
        }
        if (tid == 0) {
            out[0] = rs[0];
            g_ticket = 0;                    // reset for next graph replay
            g_flag   = 0;
        }
    }
}

extern "C" void kernel_launch(void* const* d_in, const int* in_sizes, int n_in,
                              void* d_out, int out_size) {
    const float* x  = (const float*)d_in[0];  // [8192]
    const float* wl = (const float*)d_in[1];  // [64] weight_logits
    const float* mu = (const float*)d_in[2];  // [64] means
    const float* lv = (const float*)d_in[3];  // [64] log_vars
    float* out = (float*)d_out;

    gmm_fused<<<GRID, 256>>>(x, wl, mu, lv, out);
}

// round 13
// speedup vs baseline: 1.1943x; 1.1943x over previous
#include <cuda_runtime.h>
#include <cuda_bf16.h>
#include <math_constants.h>

// Problem constants
#define NPTS    8192
#define KCOMP   64
#define NBINS   256
#define WPB     8                 // warps (j's) per main block
#define NMAIN   1024              // main blocks; block 0 is the prep block
#define GRID    (NMAIN + 1)
#define HSTR    257               // padded stride, 8 warp-private hists (bank-safe)

// KDE: bw = 0.5*128/8192 = 2^-7 exactly  ->  exp(-8192*d^2) = exp2(CKDE*d^2)
#define LOG2E 1.4426950408889634
__device__ __constant__ float CKDE = (float)(-8192.0 * LOG2E);
__device__ __constant__ float NORM = (float)(1.0 / (2.5066282746310002 * 0.0078125 * 8192.0));
// ex2.ftz -> exact 0 for |d| > 0.10327. Fixed bins: width 0.052, +/-2-bin window
// covers +/-0.104 > R. Edge clamping only EXTENDS windows -> correct for any input.
#define BIN_LO  (-6.656f)
#define BIN_IW  (19.230769230769230769f)   // 1/0.052

// Scratch (device globals — no allocation allowed)
__device__ __align__(16) float g_xs[NPTS];   // x counting-sorted by bin
__device__ int            g_binstart[NBINS + 1];
__device__ float          g_bsum[GRID];
__device__ volatile int   g_flag   = 0;      // prep-done flag; reset each call
__device__ int            g_ticket = 0;      // last-block ticket; reset each call

__device__ __forceinline__ float ex2(float x) {
    float r;
    asm("ex2.approx.ftz.f32 %0, %1;" : "=f"(r) : "f"(x));
    return r;
}

__device__ __forceinline__ int bin_of(float v) {
    int b = (int)floorf((v - BIN_LO) * BIN_IW);
    return max(min(b, NBINS - 1), 0);
}

// KEY CHANGE vs R12: cap registers so the prep branch's pressure (72 regs ->
// 3 CTAs/SM -> 2.3 waves -> serialization) can't throttle the 1024 main
// blocks. <=32 regs -> 8 CTAs/SM (thread-limited) -> single wave, all blocks
// co-resident, prep overlapped by mixture work. Prep branch spills to local
// (one block only — acceptable).
__global__ __launch_bounds__(256, 8)
void gmm_fused(const float* __restrict__ x,  const float* __restrict__ wl,
               const float* __restrict__ mu, const float* __restrict__ lv,
               float* __restrict__ out) {
    __shared__ int   h[HSTR * 8];        // prep: warp-private hists -> cursors
    __shared__ int   tot[NBINS];
    __shared__ int   bs[NBINS + 1];
    __shared__ float smn[KCOMP], scf[KCOMP], sa[KCOMP];
    __shared__ float wsum[WPB];
    __shared__ float rs[256];
    __shared__ int   s_last;

    const int tid  = threadIdx.x;
    const int lane = tid & 31;
    const int w    = tid >> 5;
    const int blk  = blockIdx.x;

    if (blk == 0) {
        // ================= PREP (sole producer) =================
        for (int i = tid; i < HSTR * 8; i += 256) h[i] = 0;
        __syncthreads();

        // pass 1: warp-private histograms (spread across 8 hists)
        for (int e = 0; e < 32; e++) {
            float v = x[tid + e * 256];
            atomicAdd(&h[bin_of(v) + HSTR * w], 1);
        }
        __syncthreads();

        // cross-warp exclusive prefix per bin (thread-per-bin, in place)
        {
            int run = 0;
            #pragma unroll
            for (int k = 0; k < 8; k++) {
                int idx = tid + HSTR * k;
                int v = h[idx];
                h[idx] = run;
                run += v;
            }
            tot[tid] = run;
        }
        __syncthreads();

        // warp 0: exclusive scan of 256 bin totals
        if (w == 0) {
            int v[8], p[8], run = 0;
            #pragma unroll
            for (int k = 0; k < 8; k++) {
                v[k] = tot[lane * 8 + k];
                p[k] = run;
                run += v[k];
            }
            int incl = run;
            #pragma unroll
            for (int o = 1; o < 32; o <<= 1) {
                int u = __shfl_up_sync(0xffffffffu, incl, o);
                if (lane >= o) incl += u;
            }
            int excl = incl - run;
            #pragma unroll
            for (int k = 0; k < 8; k++) bs[lane * 8 + k] = excl + p[k];
            if (lane == 31) bs[NBINS] = incl;      // == NPTS
        }
        __syncthreads();

        // convert warp prefixes to absolute scatter cursors
        {
            int base = bs[tid];
            #pragma unroll
            for (int k = 0; k < 8; k++) h[tid + HSTR * k] += base;
        }
        g_binstart[tid] = bs[tid];
        if (tid == 0) g_binstart[NBINS] = bs[NBINS];
        __syncthreads();

        // pass 2: scatter via cursor atomics (same elements -> unique positions)
        for (int e = 0; e < 32; e++) {
            float v = x[tid + e * 256];
            int pos = atomicAdd(&h[bin_of(v) + HSTR * w], 1);
            g_xs[pos] = v;
        }
        __syncthreads();

        if (tid == 0) {
            g_bsum[0] = 0.0f;
            __threadfence();                        // release all prep writes
            atomicExch((int*)&g_flag, 1);
        }
    } else {
        // ================= MAIN (overlaps with prep) =================
        // redundant softmax constants (race-free: direct reads of const inputs)
        if (tid < KCOMP) {
            float m = -CUDART_INF_F;
            #pragma unroll
            for (int i = 0; i < KCOMP; i++) m = fmaxf(m, __ldg(&wl[i]));
            float ss = 0.0f;
            #pragma unroll
            for (int i = 0; i < KCOMP; i++) ss += __expf(__ldg(&wl[i]) - m);
            float wgt = __expf(__ldg(&wl[tid]) - m) / ss;
            float var = __expf(lv[tid]);
            smn[tid] = mu[tid];
            scf[tid] = wgt * rsqrtf(6.283185307179586f * var);
            sa[tid]  = (float)(-0.5 * LOG2E) / var;
        }
        __syncthreads();

        // j from ORIGINAL x (no prep dependency): sum over j is permutation-invariant
        const int j = (blk - 1) * WPB + w;
        const float xj = __ldg(&x[j]);

        // mixture pdf partial (2 comps/lane) — computed BEFORE waiting on prep
        float d1 = xj - smn[lane];
        float mixp = scf[lane] * ex2(sa[lane] * d1 * d1);
        float d2 = xj - smn[lane + 32];
        mixp += scf[lane + 32] * ex2(sa[lane + 32] * d2 * d2);

        // wait for prep (volatile poll by one thread, acquire fence, release block)
        if (tid == 0) {
            while (g_flag == 0) { }
            __threadfence();
        }
        __syncthreads();

        // KDE window loop. Plain coherent loads of g_binstart/g_xs — written
        // THIS launch; __ldg here is UB (the R11 bug).
        int b  = bin_of(xj);
        int c0 = g_binstart[max(b - 2, 0)];
        int c1 = g_binstart[min(b + 3, NBINS)];

        const float ck = CKDE;
        float acc = 0.0f;
        #pragma unroll 4
        for (int i = c0 + lane; i < c1; i += 32) {
            float d = xj - g_xs[i];          // Sterbenz-exact for close pairs
            acc += ex2(ck * d * d);
        }

        // fold before reducing: sum_lanes(mixp - NORM*acc) = mixture_j - data_j
        float t = mixp - NORM * acc;
        #pragma unroll
        for (int o = 16; o > 0; o >>= 1) t += __shfl_xor_sync(0xffffffffu, t, o);
        if (lane == 0) wsum[w] = t * t;
        __syncthreads();

        if (tid == 0) {
            float v = 0.0f;
            #pragma unroll
            for (int p = 0; p < WPB; p++) v += wsum[p];
            g_bsum[blk] = v;
        }
    }

    // ================= ticket + deterministic final reduction =================
    if (tid == 0) {
        __threadfence();
        int tk = atomicAdd(&g_ticket, 1);
        s_last = (tk == GRID - 1);
    }
    __syncthreads();

    if (s_last) {
        __threadfence();                     // acquire: order reads after ticket
        float v = 0.0f;
        for (int i = tid; i < GRID; i += 256) v += g_bsum[i];
        rs[tid] = v;
        __syncthreads();
        #pragma unroll
        for (int off = 128; off > 0; off >>= 1) {
            if (tid < off) rs[tid] += rs[tid + off];
            __syncthreads();
        }
        if (tid == 0) {
            out[0] = rs[0];
            g_ticket = 0;                    // reset for next graph replay
            g_flag   = 0;
        }
    }
}

extern "C" void kernel_launch(void* const* d_in, const int* in_sizes, int n_in,
                              void* d_out, int out_size) {
    const float* x  = (const float*)d_in[0];  // [8192]
    const float* wl = (const float*)d_in[1];  // [64] weight_logits
    const float* mu = (const float*)d_in[2];  // [64] means
    const float* lv = (const float*)d_in[3];  // [64] log_vars
    float* out = (float*)d_out;

    gmm_fused<<<GRID, 256>>>(x, wl, mu, lv, out);
}